// round 9
// baseline (speedup 1.0000x reference)
#include <cuda_runtime.h>
#include <cuda_fp16.h>
#include <cstdint>
#include <math.h>

// Problem dims
#define BB 8192
#define DD 256
#define HH 512
#define KK 1280   // D + 2H
#define NN 2560   // 5H

// GEMM tiling (fp16 mma.sync m16n8k16)
#define BM 128
#define BN 128
#define BKH 64          // K per stage, in halves (128B of data per row)
#define NT (KK / BKH)   // 20
#define STRH 72         // padded smem row stride in halves (144 B)
#define STAGE_HALVES (2 * BM * STRH)            // A tile + B tile per stage
#define SMEM_BYTES  (2 * STAGE_HALVES * 2)      // 2 stages -> 73728 B

// Scratch (device globals; allocation is forbidden)
__device__ __half g_Ah[(size_t)BB * KK];     // A = [x|h_t|h_s] fp16   [8192,1280]
__device__ __half g_WTh[(size_t)NN * KK];    // W^T fp16               [2560,1280]
__device__ float  g_bias[NN];
__device__ float  g_gates[(size_t)BB * NN];  // activated gates        [8192,2560]

// ---------------------------------------------------------------------------
__device__ __forceinline__ void cp_async16_s(uint32_t saddr, const void* g) {
    asm volatile("cp.async.cg.shared.global [%0], [%1], 16;" :: "r"(saddr), "l"(g));
}
__device__ __forceinline__ uint32_t smem_to_u32(const void* p) {
    uint32_t a;
    asm("{ .reg .u64 t; cvta.to.shared.u64 t, %1; cvt.u32.u64 %0, t; }" : "=r"(a) : "l"(p));
    return a;
}
__device__ __forceinline__ float sigmoid_f(float x) {
    return 1.0f / (1.0f + __expf(-x));
}
__device__ __forceinline__ float tanh_f(float x) {
    // 2*sigmoid(2x) - 1, accurate to ~1e-7 rel
    return 2.0f / (1.0f + __expf(-2.0f * x)) - 1.0f;
}

__device__ __forceinline__ void mma_f16(float c[4], const uint32_t a[4],
                                        uint32_t b0, uint32_t b1) {
    asm volatile(
        "mma.sync.aligned.m16n8k16.row.col.f32.f16.f16.f32 "
        "{%0,%1,%2,%3}, {%4,%5,%6,%7}, {%8,%9}, {%0,%1,%2,%3};"
        : "+f"(c[0]), "+f"(c[1]), "+f"(c[2]), "+f"(c[3])
        : "r"(a[0]), "r"(a[1]), "r"(a[2]), "r"(a[3]),
          "r"(b0), "r"(b1));
}

// ---------------------------------------------------------------------------
// pack_A: A = [x | h_t | h_s] -> fp16. Each thread converts 4 elements.
// ---------------------------------------------------------------------------
__global__ void pack_A_kernel(const float* __restrict__ x,
                              const float* __restrict__ ht,
                              const float* __restrict__ hs) {
    int idx = blockIdx.x * blockDim.x + threadIdx.x;
    const int total = BB * KK / 4;
    if (idx >= total) return;
    int b  = idx / (KK / 4);
    int k4 = (idx % (KK / 4)) * 4;
    float4 v;
    if (k4 < DD)              v = *(const float4*)(x  + (size_t)b * DD + k4);
    else if (k4 < DD + HH)    v = *(const float4*)(ht + (size_t)b * HH + (k4 - DD));
    else                      v = *(const float4*)(hs + (size_t)b * HH + (k4 - DD - HH));
    __half2 lo = __floats2half2_rn(v.x, v.y);
    __half2 hi = __floats2half2_rn(v.z, v.w);
    uint2 packed = make_uint2(*(uint32_t*)&lo, *(uint32_t*)&hi);
    *(uint2*)(g_Ah + (size_t)b * KK + k4) = packed;
}

// ---------------------------------------------------------------------------
// pack_WT: WT[n][k] = concat-W[k][n] -> fp16 (transpose via smem). + bias.
// ---------------------------------------------------------------------------
__global__ void pack_WT_kernel(
    const float* Ui, const float* Us, const float* Ut, const float* Uo, const float* Uc,
    const float* Wti, const float* Wts, const float* Wtt, const float* Wto, const float* Wtc,
    const float* Wsi, const float* Wss, const float* Wst, const float* Wso, const float* Wsc,
    const float* bi, const float* bs, const float* bt, const float* bo, const float* bc) {
    __shared__ float t[32][33];
    const float* Ua[5]  = {Ui, Us, Ut, Uo, Uc};
    const float* Wta[5] = {Wti, Wts, Wtt, Wto, Wtc};
    const float* Wsa[5] = {Wsi, Wss, Wst, Wso, Wsc};

    int kb = blockIdx.x * 32;   // K block
    int nb = blockIdx.y * 32;   // N block
#pragma unroll
    for (int i = 0; i < 4; i++) {
        int k = kb + threadIdx.y + i * 8;
        int n = nb + threadIdx.x;
        int g = n >> 9, j = n & 511;
        const float* src; int kk;
        if (k < DD)           { src = Ua[g];  kk = k; }
        else if (k < DD + HH) { src = Wta[g]; kk = k - DD; }
        else                  { src = Wsa[g]; kk = k - DD - HH; }
        t[threadIdx.y + i * 8][threadIdx.x] = src[(size_t)kk * HH + j];
    }
    __syncthreads();
#pragma unroll
    for (int i = 0; i < 4; i++) {
        int n = nb + threadIdx.y + i * 8;
        int k = kb + threadIdx.x;
        g_WTh[(size_t)n * KK + k] = __float2half_rn(t[threadIdx.x][threadIdx.y + i * 8]);
    }
    if (blockIdx.x == 0 && blockIdx.y == 0) {
        const float* ba[5] = {bi, bs, bt, bo, bc};
        int tid = threadIdx.y * 32 + threadIdx.x;
        for (int idx = tid; idx < NN; idx += 256)
            g_bias[idx] = ba[idx >> 9][idx & 511];
    }
}

// ---------------------------------------------------------------------------
// GEMM: gates = act(A @ W + bias).  fp16 mma.sync m16n8k16, 128x128x64 tiles,
// 8 warps (4x2), warp tile 32x64, cp.async double buffer.
// ---------------------------------------------------------------------------
__global__ void __launch_bounds__(256, 2)
gemm_gates_kernel() {
    extern __shared__ __half smem[];
    __half* As0 = smem;                        // [2][128][STRH]
    uint32_t sbase = smem_to_u32(smem);

    const int tid  = threadIdx.x;
    const int warp = tid >> 5;
    const int lane = tid & 31;
    const int wm = warp >> 1;     // 0..3
    const int wn = warp & 1;      // 0..1
    const int lr = lane >> 2;     // 0..7
    const int lc = lane & 3;      // 0..3

    const int brow = blockIdx.y * BM;
    const int bcol = blockIdx.x * BN;

    float acc[2][8][4];
#pragma unroll
    for (int mi = 0; mi < 2; mi++)
#pragma unroll
        for (int ni = 0; ni < 8; ni++)
#pragma unroll
            for (int q = 0; q < 4; q++) acc[mi][ni][q] = 0.f;

    const __half* Agb = g_Ah  + (size_t)brow * KK;
    const __half* Bgb = g_WTh + (size_t)bcol * KK;

    // stage loader: A 128 rows x 64 halves, B 128 rows x 64 halves, 16B chunks
    auto load_tile = [&](int kt, int stage) {
        uint32_t sA = sbase + stage * STAGE_HALVES * 2;
        uint32_t sB = sA + BM * STRH * 2;
        int kbase = kt * BKH;
#pragma unroll
        for (int p = 0; p < 4; p++) {
            int id = p * 256 + tid;
            int r = id >> 3, c = id & 7;                       // 8 chunks of 16B per row
            cp_async16_s(sA + r * (STRH * 2) + c * 16,
                         Agb + (size_t)r * KK + kbase + c * 8);
        }
#pragma unroll
        for (int p = 0; p < 4; p++) {
            int id = p * 256 + tid;
            int r = id >> 3, c = id & 7;
            cp_async16_s(sB + r * (STRH * 2) + c * 16,
                         Bgb + (size_t)r * KK + kbase + c * 8);
        }
        asm volatile("cp.async.commit_group;" ::: "memory");
    };

    load_tile(0, 0);
    asm volatile("cp.async.wait_group 0;" ::: "memory");
    __syncthreads();

    for (int kt = 0; kt < NT; kt++) {
        if (kt + 1 < NT) load_tile(kt + 1, (kt + 1) & 1);

        const __half* As = As0 + (kt & 1) * STAGE_HALVES;
        const __half* Bs = As + BM * STRH;

#pragma unroll
        for (int kk = 0; kk < 4; kk++) {
            const int k0 = kk * 16;
            uint32_t a[2][4];
#pragma unroll
            for (int mi = 0; mi < 2; mi++) {
                int row = wm * 32 + mi * 16 + lr;
                a[mi][0] = *(const uint32_t*)(As + row * STRH + k0 + lc * 2);
                a[mi][1] = *(const uint32_t*)(As + (row + 8) * STRH + k0 + lc * 2);
                a[mi][2] = *(const uint32_t*)(As + row * STRH + k0 + 8 + lc * 2);
                a[mi][3] = *(const uint32_t*)(As + (row + 8) * STRH + k0 + 8 + lc * 2);
            }
            uint32_t b0[8], b1[8];
#pragma unroll
            for (int ni = 0; ni < 8; ni++) {
                int col = wn * 64 + ni * 8 + lr;
                b0[ni] = *(const uint32_t*)(Bs + col * STRH + k0 + lc * 2);
                b1[ni] = *(const uint32_t*)(Bs + col * STRH + k0 + 8 + lc * 2);
            }
#pragma unroll
            for (int mi = 0; mi < 2; mi++)
#pragma unroll
                for (int ni = 0; ni < 8; ni++)
                    mma_f16(acc[mi][ni], a[mi], b0[ni], b1[ni]);
        }
        asm volatile("cp.async.wait_group 0;" ::: "memory");
        __syncthreads();
    }

    // Epilogue: bias + activation (gates 0-3 sigmoid, gate 4 tanh).
    const bool use_tanh = ((bcol >> 9) == 4);
#pragma unroll
    for (int mi = 0; mi < 2; mi++) {
        int row = brow + wm * 32 + mi * 16 + lr;
#pragma unroll
        for (int ni = 0; ni < 8; ni++) {
            int col = bcol + wn * 64 + ni * 8 + lc * 2;
            float bb0 = g_bias[col], bb1 = g_bias[col + 1];
            float v0 = acc[mi][ni][0] + bb0;
            float v1 = acc[mi][ni][1] + bb1;
            float v2 = acc[mi][ni][2] + bb0;
            float v3 = acc[mi][ni][3] + bb1;
            if (use_tanh) {
                v0 = tanh_f(v0); v1 = tanh_f(v1); v2 = tanh_f(v2); v3 = tanh_f(v3);
            } else {
                v0 = sigmoid_f(v0); v1 = sigmoid_f(v1);
                v2 = sigmoid_f(v2); v3 = sigmoid_f(v3);
            }
            *(float2*)(g_gates + (size_t)row * NN + col)       = make_float2(v0, v1);
            *(float2*)(g_gates + (size_t)(row + 8) * NN + col) = make_float2(v2, v3);
        }
    }
}

// ---------------------------------------------------------------------------
// combine: c_h = i*c_n + f_t*c_t + f_s*c_s ;  h = o * tanh(c_h)
// out = [h (B*H) ; c_h (B*H)]
// ---------------------------------------------------------------------------
__global__ void combine_kernel(const float* __restrict__ ct,
                               const float* __restrict__ cs,
                               float* __restrict__ out) {
    int idx = blockIdx.x * blockDim.x + threadIdx.x;
    const int total = BB * HH / 4;
    if (idx >= total) return;
    int b  = idx / (HH / 4);
    int j4 = (idx % (HH / 4)) * 4;
    const float* grow = g_gates + (size_t)b * NN;

    float4 gi = *(const float4*)(grow + j4);            // i
    float4 fs = *(const float4*)(grow + 512 + j4);      // f_s
    float4 ft = *(const float4*)(grow + 1024 + j4);     // f_t
    float4 go = *(const float4*)(grow + 1536 + j4);     // o
    float4 cn = *(const float4*)(grow + 2048 + j4);     // c_n (tanh'd)
    float4 ctv = *(const float4*)(ct + (size_t)b * HH + j4);
    float4 csv = *(const float4*)(cs + (size_t)b * HH + j4);

    float4 ch, h;
    ch.x = gi.x * cn.x + ft.x * ctv.x + fs.x * csv.x;  h.x = go.x * tanh_f(ch.x);
    ch.y = gi.y * cn.y + ft.y * ctv.y + fs.y * csv.y;  h.y = go.y * tanh_f(ch.y);
    ch.z = gi.z * cn.z + ft.z * ctv.z + fs.z * csv.z;  h.z = go.z * tanh_f(ch.z);
    ch.w = gi.w * cn.w + ft.w * ctv.w + fs.w * csv.w;  h.w = go.w * tanh_f(ch.w);

    *(float4*)(out + (size_t)b * HH + j4) = h;
    *(float4*)(out + (size_t)BB * HH + (size_t)b * HH + j4) = ch;
}

// ---------------------------------------------------------------------------
extern "C" void kernel_launch(void* const* d_in, const int* in_sizes, int n_in,
                              void* d_out, int out_size) {
    const float* x   = (const float*)d_in[0];
    const float* h_t = (const float*)d_in[1];
    const float* h_s = (const float*)d_in[2];
    const float* c_t = (const float*)d_in[3];
    const float* c_s = (const float*)d_in[4];
    const float* Ui  = (const float*)d_in[5];
    const float* Wti = (const float*)d_in[6];
    const float* Wsi = (const float*)d_in[7];
    const float* bi  = (const float*)d_in[8];
    const float* Us  = (const float*)d_in[9];
    const float* Wts = (const float*)d_in[10];
    const float* Wss = (const float*)d_in[11];
    const float* bs  = (const float*)d_in[12];
    const float* Ut  = (const float*)d_in[13];
    const float* Wtt = (const float*)d_in[14];
    const float* Wst = (const float*)d_in[15];
    const float* bt  = (const float*)d_in[16];
    const float* Uo  = (const float*)d_in[17];
    const float* Wto = (const float*)d_in[18];
    const float* Wso = (const float*)d_in[19];
    const float* bo  = (const float*)d_in[20];
    const float* Uc  = (const float*)d_in[21];
    const float* Wtc = (const float*)d_in[22];
    const float* Wsc = (const float*)d_in[23];
    const float* bc  = (const float*)d_in[24];
    float* out = (float*)d_out;

    // pack A (fp16)
    {
        int total = BB * KK / 4;
        pack_A_kernel<<<(total + 255) / 256, 256>>>(x, h_t, h_s);
    }
    // pack W^T (fp16) + bias
    {
        dim3 grid(KK / 32, NN / 32);   // (40, 80)
        pack_WT_kernel<<<grid, dim3(32, 8)>>>(
            Ui, Us, Ut, Uo, Uc,
            Wti, Wts, Wtt, Wto, Wtc,
            Wsi, Wss, Wst, Wso, Wsc,
            bi, bs, bt, bo, bc);
    }
    // GEMM (fp16 mma.sync)
    {
        cudaFuncSetAttribute(gemm_gates_kernel,
                             cudaFuncAttributeMaxDynamicSharedMemorySize, SMEM_BYTES);
        dim3 grid(NN / BN, BB / BM);   // (20, 64)
        gemm_gates_kernel<<<grid, 256, SMEM_BYTES>>>();
    }
    // combine
    {
        int total = BB * HH / 4;
        combine_kernel<<<(total + 255) / 256, 256>>>(c_t, c_s, out);
    }
}

// round 10
// speedup vs baseline: 1.0707x; 1.0707x over previous
#include <cuda_runtime.h>
#include <cuda_fp16.h>
#include <cstdint>
#include <math.h>

// Problem dims
#define BB 8192
#define DD 256
#define HH 512
#define KK 1280   // D + 2H
#define NN 2560   // 5H

// GEMM tiling (fp16 mma.sync m16n8k16)
#define BM 128
#define BN 128
#define BKH 64          // K per stage, in halves (128B of data per row)
#define NT (KK / BKH)   // 20
#define STRH 72         // padded smem row stride in halves (144 B)
#define STRB 144        // row stride bytes
#define STAGE_BYTES (2 * BM * STRH * 2)         // A tile + B tile per stage = 36864
#define SMEM_BYTES  (2 * STAGE_BYTES)           // 2 stages -> 73728 B

// Scratch (device globals; allocation is forbidden)
__device__ __half g_Ah[(size_t)BB * KK];     // A = [x|h_t|h_s] fp16   [8192,1280]
__device__ __half g_WTh[(size_t)NN * KK];    // W^T fp16               [2560,1280]
__device__ float  g_bias[NN];
__device__ __half g_gates[(size_t)BB * NN];  // activated gates fp16   [8192,2560]

// ---------------------------------------------------------------------------
__device__ __forceinline__ void cp_async16_s(uint32_t saddr, const void* g) {
    asm volatile("cp.async.cg.shared.global [%0], [%1], 16;" :: "r"(saddr), "l"(g));
}
__device__ __forceinline__ uint32_t smem_to_u32(const void* p) {
    uint32_t a;
    asm("{ .reg .u64 t; cvta.to.shared.u64 t, %1; cvt.u32.u64 %0, t; }" : "=r"(a) : "l"(p));
    return a;
}
__device__ __forceinline__ float sigmoid_f(float x) {
    return 1.0f / (1.0f + __expf(-x));
}
__device__ __forceinline__ float tanh_f(float x) {
    return 2.0f / (1.0f + __expf(-2.0f * x)) - 1.0f;
}
__device__ __forceinline__ void ldsm_x4(uint32_t r[4], uint32_t addr) {
    asm volatile("ldmatrix.sync.aligned.m8n8.x4.shared.b16 {%0,%1,%2,%3}, [%4];"
                 : "=r"(r[0]), "=r"(r[1]), "=r"(r[2]), "=r"(r[3]) : "r"(addr));
}
__device__ __forceinline__ void mma_f16(float c[4], const uint32_t a[4],
                                        uint32_t b0, uint32_t b1) {
    asm volatile(
        "mma.sync.aligned.m16n8k16.row.col.f32.f16.f16.f32 "
        "{%0,%1,%2,%3}, {%4,%5,%6,%7}, {%8,%9}, {%0,%1,%2,%3};"
        : "+f"(c[0]), "+f"(c[1]), "+f"(c[2]), "+f"(c[3])
        : "r"(a[0]), "r"(a[1]), "r"(a[2]), "r"(a[3]),
          "r"(b0), "r"(b1));
}

// ---------------------------------------------------------------------------
// pack_A: A = [x | h_t | h_s] -> fp16. Each thread converts 4 elements.
// ---------------------------------------------------------------------------
__global__ void pack_A_kernel(const float* __restrict__ x,
                              const float* __restrict__ ht,
                              const float* __restrict__ hs) {
    int idx = blockIdx.x * blockDim.x + threadIdx.x;
    const int total = BB * KK / 4;
    if (idx >= total) return;
    int b  = idx / (KK / 4);
    int k4 = (idx % (KK / 4)) * 4;
    float4 v;
    if (k4 < DD)              v = *(const float4*)(x  + (size_t)b * DD + k4);
    else if (k4 < DD + HH)    v = *(const float4*)(ht + (size_t)b * HH + (k4 - DD));
    else                      v = *(const float4*)(hs + (size_t)b * HH + (k4 - DD - HH));
    __half2 lo = __floats2half2_rn(v.x, v.y);
    __half2 hi = __floats2half2_rn(v.z, v.w);
    uint2 packed = make_uint2(*(uint32_t*)&lo, *(uint32_t*)&hi);
    *(uint2*)(g_Ah + (size_t)b * KK + k4) = packed;
}

// ---------------------------------------------------------------------------
// pack_WT: WT[n][k] = concat-W[k][n] -> fp16 (transpose via smem). + bias.
// ---------------------------------------------------------------------------
__global__ void pack_WT_kernel(
    const float* Ui, const float* Us, const float* Ut, const float* Uo, const float* Uc,
    const float* Wti, const float* Wts, const float* Wtt, const float* Wto, const float* Wtc,
    const float* Wsi, const float* Wss, const float* Wst, const float* Wso, const float* Wsc,
    const float* bi, const float* bs, const float* bt, const float* bo, const float* bc) {
    __shared__ float t[32][33];
    const float* Ua[5]  = {Ui, Us, Ut, Uo, Uc};
    const float* Wta[5] = {Wti, Wts, Wtt, Wto, Wtc};
    const float* Wsa[5] = {Wsi, Wss, Wst, Wso, Wsc};

    int kb = blockIdx.x * 32;   // K block
    int nb = blockIdx.y * 32;   // N block
#pragma unroll
    for (int i = 0; i < 4; i++) {
        int k = kb + threadIdx.y + i * 8;
        int n = nb + threadIdx.x;
        int g = n >> 9, j = n & 511;
        const float* src; int kk;
        if (k < DD)           { src = Ua[g];  kk = k; }
        else if (k < DD + HH) { src = Wta[g]; kk = k - DD; }
        else                  { src = Wsa[g]; kk = k - DD - HH; }
        t[threadIdx.y + i * 8][threadIdx.x] = src[(size_t)kk * HH + j];
    }
    __syncthreads();
#pragma unroll
    for (int i = 0; i < 4; i++) {
        int n = nb + threadIdx.y + i * 8;
        int k = kb + threadIdx.x;
        g_WTh[(size_t)n * KK + k] = __float2half_rn(t[threadIdx.x][threadIdx.y + i * 8]);
    }
    if (blockIdx.x == 0 && blockIdx.y == 0) {
        const float* ba[5] = {bi, bs, bt, bo, bc};
        int tid = threadIdx.y * 32 + threadIdx.x;
        for (int idx = tid; idx < NN; idx += 256)
            g_bias[idx] = ba[idx >> 9][idx & 511];
    }
}

// ---------------------------------------------------------------------------
// GEMM: gates = act(A @ W + bias).  fp16 mma.sync m16n8k16, 128x128x64 tiles,
// 8 warps (4x2), warp tile 32x64, cp.async double buffer, ldmatrix fragments.
// ---------------------------------------------------------------------------
__global__ void __launch_bounds__(256, 2)
gemm_gates_kernel() {
    extern __shared__ __half smem[];
    uint32_t sbase = smem_to_u32(smem);

    const int tid  = threadIdx.x;
    const int warp = tid >> 5;
    const int lane = tid & 31;
    const int wm = warp >> 1;     // 0..3
    const int wn = warp & 1;      // 0..1
    const int lr = lane >> 2;     // 0..7
    const int lc = lane & 3;      // 0..3

    const int brow = blockIdx.y * BM;
    const int bcol = blockIdx.x * BN;

    // ldmatrix per-lane byte offsets within stage tiles
    const int l7 = lane & 7;
    // A: lanes 0-7 rows+k0 | 8-15 rows+8,k0 | 16-23 rows,k0+8 | 24-31 rows+8,k0+8
    const uint32_t offA = (uint32_t)(wm * 32 + l7 + ((lane >> 3) & 1) * 8) * STRB
                        + ((lane >> 4) & 1) * 16;
    // B: lanes 0-7 cols,k0 | 8-15 cols,k0+8 | 16-23 cols+8,k0 | 24-31 cols+8,k0+8
    const uint32_t offB = (uint32_t)(wn * 64 + l7 + ((lane >> 4) & 1) * 8) * STRB
                        + ((lane >> 3) & 1) * 16;

    float acc[2][8][4];
#pragma unroll
    for (int mi = 0; mi < 2; mi++)
#pragma unroll
        for (int ni = 0; ni < 8; ni++)
#pragma unroll
            for (int q = 0; q < 4; q++) acc[mi][ni][q] = 0.f;

    const __half* Agb = g_Ah  + (size_t)brow * KK;
    const __half* Bgb = g_WTh + (size_t)bcol * KK;

    auto load_tile = [&](int kt, int stage) {
        uint32_t sA = sbase + stage * STAGE_BYTES;
        uint32_t sB = sA + BM * STRB;
        int kbase = kt * BKH;
#pragma unroll
        for (int p = 0; p < 4; p++) {
            int id = p * 256 + tid;
            int r = id >> 3, c = id & 7;
            cp_async16_s(sA + r * STRB + c * 16,
                         Agb + (size_t)r * KK + kbase + c * 8);
        }
#pragma unroll
        for (int p = 0; p < 4; p++) {
            int id = p * 256 + tid;
            int r = id >> 3, c = id & 7;
            cp_async16_s(sB + r * STRB + c * 16,
                         Bgb + (size_t)r * KK + kbase + c * 8);
        }
        asm volatile("cp.async.commit_group;" ::: "memory");
    };

    load_tile(0, 0);
    asm volatile("cp.async.wait_group 0;" ::: "memory");
    __syncthreads();

    for (int kt = 0; kt < NT; kt++) {
        if (kt + 1 < NT) load_tile(kt + 1, (kt + 1) & 1);

        uint32_t sA = sbase + (kt & 1) * STAGE_BYTES;
        uint32_t sB = sA + BM * STRB;

#pragma unroll
        for (int kk = 0; kk < 4; kk++) {
            const uint32_t kb = kk * 32;    // k0 bytes
            uint32_t a[2][4];
#pragma unroll
            for (int mi = 0; mi < 2; mi++)
                ldsm_x4(a[mi], sA + offA + mi * 16 * STRB + kb);

            uint32_t b0[8], b1[8];
#pragma unroll
            for (int q = 0; q < 4; q++) {
                uint32_t r[4];
                ldsm_x4(r, sB + offB + q * 16 * STRB + kb);
                b0[2 * q]     = r[0];  b1[2 * q]     = r[1];
                b0[2 * q + 1] = r[2];  b1[2 * q + 1] = r[3];
            }
#pragma unroll
            for (int mi = 0; mi < 2; mi++)
#pragma unroll
                for (int ni = 0; ni < 8; ni++)
                    mma_f16(acc[mi][ni], a[mi], b0[ni], b1[ni]);
        }
        asm volatile("cp.async.wait_group 0;" ::: "memory");
        __syncthreads();
    }

    // Epilogue: bias + activation, fp16 gate store.
    const bool use_tanh = ((bcol >> 9) == 4);
#pragma unroll
    for (int mi = 0; mi < 2; mi++) {
        int row = brow + wm * 32 + mi * 16 + lr;
#pragma unroll
        for (int ni = 0; ni < 8; ni++) {
            int col = bcol + wn * 64 + ni * 8 + lc * 2;
            float bb0 = g_bias[col], bb1 = g_bias[col + 1];
            float v0 = acc[mi][ni][0] + bb0;
            float v1 = acc[mi][ni][1] + bb1;
            float v2 = acc[mi][ni][2] + bb0;
            float v3 = acc[mi][ni][3] + bb1;
            if (use_tanh) {
                v0 = tanh_f(v0); v1 = tanh_f(v1); v2 = tanh_f(v2); v3 = tanh_f(v3);
            } else {
                v0 = sigmoid_f(v0); v1 = sigmoid_f(v1);
                v2 = sigmoid_f(v2); v3 = sigmoid_f(v3);
            }
            __half2 lo = __floats2half2_rn(v0, v1);
            __half2 hi = __floats2half2_rn(v2, v3);
            *(__half2*)(g_gates + (size_t)row * NN + col)       = lo;
            *(__half2*)(g_gates + (size_t)(row + 8) * NN + col) = hi;
        }
    }
}

// ---------------------------------------------------------------------------
// combine: c_h = i*c_n + f_t*c_t + f_s*c_s ;  h = o * tanh(c_h)
// out = [h (B*H) ; c_h (B*H)]
// ---------------------------------------------------------------------------
__device__ __forceinline__ float4 ld_gate4(const __half* p) {
    uint2 u = *(const uint2*)p;
    __half2 lo = *(__half2*)&u.x, hi = *(__half2*)&u.y;
    float2 a = __half22float2(lo), b = __half22float2(hi);
    return make_float4(a.x, a.y, b.x, b.y);
}

__global__ void combine_kernel(const float* __restrict__ ct,
                               const float* __restrict__ cs,
                               float* __restrict__ out) {
    int idx = blockIdx.x * blockDim.x + threadIdx.x;
    const int total = BB * HH / 4;
    if (idx >= total) return;
    int b  = idx / (HH / 4);
    int j4 = (idx % (HH / 4)) * 4;
    const __half* grow = g_gates + (size_t)b * NN;

    float4 gi = ld_gate4(grow + j4);            // i
    float4 fs = ld_gate4(grow + 512 + j4);      // f_s
    float4 ft = ld_gate4(grow + 1024 + j4);     // f_t
    float4 go = ld_gate4(grow + 1536 + j4);     // o
    float4 cn = ld_gate4(grow + 2048 + j4);     // c_n (tanh'd)
    float4 ctv = *(const float4*)(ct + (size_t)b * HH + j4);
    float4 csv = *(const float4*)(cs + (size_t)b * HH + j4);

    float4 ch, h;
    ch.x = gi.x * cn.x + ft.x * ctv.x + fs.x * csv.x;  h.x = go.x * tanh_f(ch.x);
    ch.y = gi.y * cn.y + ft.y * ctv.y + fs.y * csv.y;  h.y = go.y * tanh_f(ch.y);
    ch.z = gi.z * cn.z + ft.z * ctv.z + fs.z * csv.z;  h.z = go.z * tanh_f(ch.z);
    ch.w = gi.w * cn.w + ft.w * ctv.w + fs.w * csv.w;  h.w = go.w * tanh_f(ch.w);

    *(float4*)(out + (size_t)b * HH + j4) = h;
    *(float4*)(out + (size_t)BB * HH + (size_t)b * HH + j4) = ch;
}

// ---------------------------------------------------------------------------
extern "C" void kernel_launch(void* const* d_in, const int* in_sizes, int n_in,
                              void* d_out, int out_size) {
    const float* x   = (const float*)d_in[0];
    const float* h_t = (const float*)d_in[1];
    const float* h_s = (const float*)d_in[2];
    const float* c_t = (const float*)d_in[3];
    const float* c_s = (const float*)d_in[4];
    const float* Ui  = (const float*)d_in[5];
    const float* Wti = (const float*)d_in[6];
    const float* Wsi = (const float*)d_in[7];
    const float* bi  = (const float*)d_in[8];
    const float* Us  = (const float*)d_in[9];
    const float* Wts = (const float*)d_in[10];
    const float* Wss = (const float*)d_in[11];
    const float* bs  = (const float*)d_in[12];
    const float* Ut  = (const float*)d_in[13];
    const float* Wtt = (const float*)d_in[14];
    const float* Wst = (const float*)d_in[15];
    const float* bt  = (const float*)d_in[16];
    const float* Uo  = (const float*)d_in[17];
    const float* Wto = (const float*)d_in[18];
    const float* Wso = (const float*)d_in[19];
    const float* bo  = (const float*)d_in[20];
    const float* Uc  = (const float*)d_in[21];
    const float* Wtc = (const float*)d_in[22];
    const float* Wsc = (const float*)d_in[23];
    const float* bc  = (const float*)d_in[24];
    float* out = (float*)d_out;

    // pack A (fp16)
    {
        int total = BB * KK / 4;
        pack_A_kernel<<<(total + 255) / 256, 256>>>(x, h_t, h_s);
    }
    // pack W^T (fp16) + bias
    {
        dim3 grid(KK / 32, NN / 32);   // (40, 80)
        pack_WT_kernel<<<grid, dim3(32, 8)>>>(
            Ui, Us, Ut, Uo, Uc,
            Wti, Wts, Wtt, Wto, Wtc,
            Wsi, Wss, Wst, Wso, Wsc,
            bi, bs, bt, bo, bc);
    }
    // GEMM (fp16 mma.sync + ldmatrix)
    {
        cudaFuncSetAttribute(gemm_gates_kernel,
                             cudaFuncAttributeMaxDynamicSharedMemorySize, SMEM_BYTES);
        dim3 grid(NN / BN, BB / BM);   // (20, 64)
        gemm_gates_kernel<<<grid, 256, SMEM_BYTES>>>();
    }
    // combine
    {
        int total = BB * HH / 4;
        combine_kernel<<<(total + 255) / 256, 256>>>(c_t, c_s, out);
    }
}